// round 14
// baseline (speedup 1.0000x reference)
#include <cuda_runtime.h>
#include <cuda_bf16.h>
#include <math.h>

// Attention path collapses (softmax rows sum to 1; T,S fully contracted):
//   y = 1024 * (h_pred @ Wv + bv)
// Only Wv/Wo projection + gate MLP + mixer MLP survive.
//
// R12: R11 + S1/S3 merged into ONE phase via unit-aligned slice assignment:
//   S1      -> slices 0-2 (6/6/4 8k-steps), partial slots 0-2  (v)
//   gW1top  -> slices 3-5 (6/6/4),          partial slots 3-5  (g1 part)
//   gW1bot  -> slices 6-7 (8/8),            partial slots 6-7  (g1 part)
// One 32KB partial buffer, 48KB static smem, 9 barriers (was 10), merged
// reduce does 16 LDS instead of 32. P1 is a single rolled loop with
// warp-uniform (mat, act, kstart, nsteps) — no code duplication.

#define HID 128
#define ROWS 8
#define SLICES 8
#define NNODES 1024
#define NTHREADS 512

typedef unsigned long long u64;

__device__ __forceinline__ u64 fma2(u64 a, u64 b, u64 c) {
    u64 d;
    asm("fma.rn.f32x2 %0, %1, %2, %3;" : "=l"(d) : "l"(a), "l"(b), "l"(c));
    return d;
}

// Load 8 k-steps of weights for both owned columns.
__device__ __forceinline__ void loadW(const float* __restrict__ W, int c0,
                                      int c1, int k, float w0[8], float w1[8]) {
#pragma unroll
    for (int i = 0; i < 8; i++) {
        w0[i] = W[(k + i) * HID + c0];
        w1[i] = W[(k + i) * HID + c1];
    }
}

// 8 k-steps: two broadcast LDS.128 per k serve 8 FFMA2 (8 rows x 2 cols).
__device__ __forceinline__ void fma8(const float* __restrict__ act, int k,
                                     const float w0[8], const float w1[8],
                                     u64 acc[8]) {
#pragma unroll
    for (int i = 0; i < 8; i++) {
        u64 ww0, ww1;
        asm("mov.b64 %0, {%1, %1};" : "=l"(ww0) : "f"(w0[i]));
        asm("mov.b64 %0, {%1, %1};" : "=l"(ww1) : "f"(w1[i]));
        const ulonglong2* a = (const ulonglong2*)(act + (k + i) * ROWS);
        ulonglong2 a01 = a[0];   // rows 0..3
        ulonglong2 a23 = a[1];   // rows 4..7
        acc[0] = fma2(a01.x, ww0, acc[0]);
        acc[1] = fma2(a01.y, ww0, acc[1]);
        acc[2] = fma2(a23.x, ww0, acc[2]);
        acc[3] = fma2(a23.y, ww0, acc[3]);
        acc[4] = fma2(a01.x, ww1, acc[4]);
        acc[5] = fma2(a01.y, ww1, acc[5]);
        acc[6] = fma2(a23.x, ww1, acc[6]);
        acc[7] = fma2(a23.y, ww1, acc[7]);
    }
}

__device__ __forceinline__ void part_store(float* d0, float* d1,
                                           const u64 acc[8]) {
    ((ulonglong2*)d0)[0] = make_ulonglong2(acc[0], acc[1]);
    ((ulonglong2*)d0)[1] = make_ulonglong2(acc[2], acc[3]);
    ((ulonglong2*)d1)[0] = make_ulonglong2(acc[4], acc[5]);
    ((ulonglong2*)d1)[1] = make_ulonglong2(acc[6], acc[7]);
}

extern "C" __global__ void __launch_bounds__(NTHREADS, 1)
temporal_attn_fused(const float* __restrict__ h_prev,
                    const float* __restrict__ h_pred,
                    const float* __restrict__ Wv, const float* __restrict__ bv,
                    const float* __restrict__ Wo, const float* __restrict__ bo,
                    const float* __restrict__ gW1, const float* __restrict__ gb1,
                    const float* __restrict__ gW2, const float* __restrict__ gb2,
                    const float* __restrict__ mW1, const float* __restrict__ mb1,
                    const float* __restrict__ mW2, const float* __restrict__ mb2,
                    float* __restrict__ out) {
    __shared__ float bufA[HID * ROWS];          // 4KB  h_pred, later h_corr
    __shared__ float hvF[HID * ROWS];           // 4KB  h_prev
    __shared__ float bufC[HID * ROWS];          // 4KB  v, later m1
    __shared__ float g1F[HID * ROWS];           // 4KB  gate hidden
    __shared__ float pA[SLICES * HID * ROWS];   // 32KB partials

    const int tid = threadIdx.x;
    const int lane = tid & 31;
    const int wid = tid >> 5;
    const int s = wid >> 1;                 // k-slice 0..7 (warp-uniform)
    const int c0 = (wid & 1) * 32 + lane;   // first owned column (0..63)
    const int c1 = c0 + 64;                 // second owned column
    const int k0 = s * 16;
    const int r0 = blockIdx.x * ROWS;
    const int p0 = tid, p1 = tid + NTHREADS;   // elements owned in reduces
    const int q0 = p0 >> 3, q1 = p1 >> 3;      // their column indices

    // Hoisted bias loads (off the post-barrier critical paths).
    const float bv0 = bv[q0], bv1 = bv[q1];
    const float bo0 = bo[q0], bo1 = bo[q1];
    const float gb10 = gb1[q0], gb11 = gb1[q1];
    const float gb20 = gb2[q0], gb21 = gb2[q1];
    const float mb10 = mb1[q0], mb11 = mb1[q1];
    const float mb20 = mb2[q0], mb21 = mb2[q1];

    // ---- P1 schedule (unit-aligned, warp-uniform) ----
    // slices 0-2: S1 = hp@Wv     kstart {0,48,96},  nsteps {6,6,4}
    // slices 3-5: hp@gW1top      kstart {0,48,96},  nsteps {6,6,4}
    // slices 6-7: hv@gW1bot      kstart {0,64},     nsteps {8,8}
    const float* gt = gW1;
    const float* gb = gW1 + HID * HID;
    const float* matP1 = (s < 3) ? Wv : ((s < 6) ? gt : gb);
    const float* actP1s = 0;  // set after smem decl use — see below
    int kst, ns;
    if (s < 6) { int j = (s < 3) ? s : s - 3; kst = j * 48; ns = (j == 2) ? 4 : 6; }
    else       { kst = (s - 6) * 64; ns = 8; }
    if (s == 2 || s == 5) kst = 96;   // 4-step slices start at 96

    float wp0[8], wp1[8], wt0[8], wt1[8];
    loadW(matP1, c0, c1, kst, wp0, wp1);    // P1 chunk0, in flight now

    // Stage input tiles transposed: [k][r], coalesced global reads.
#pragma unroll
    for (int j = 0; j < 2; j++) {
        int g = tid + j * NTHREADS;
        int r = g >> 7, cc = g & (HID - 1);
        bufA[cc * ROWS + r] = h_pred[(r0 + r) * HID + cc];
        hvF[cc * ROWS + r]  = h_prev[(r0 + r) * HID + cc];
    }
    __syncthreads();                              // bar0

    u64 acc[8];
    float* pD0 = pA + s * 1024 + c0 * ROWS;
    float* pD1 = pA + s * 1024 + c1 * ROWS;
    const float* actP1 = (s < 6) ? bufA : hvF;

#define GEMM_ZERO() { acc[0]=acc[1]=acc[2]=acc[3]=acc[4]=acc[5]=acc[6]=acc[7]=0ULL; }

    float outv0, outv1, hcv0, hcv1;
    const float* Wm = (s < 4) ? Wo : gW2;      // P2 merged-stage matrix
    const int k0m = (s & 3) * 32;              // P2 merged-stage k-offset

    // ======== P1: S1 -> slots 0-2 ; S3 (both halves) -> slots 3-7 ========
    GEMM_ZERO();
    {
        int kk = kst;
        const int iters = (ns >> 1) - 1;       // 2, 1, or 3 (warp-uniform)
        for (int i = 0; i < iters; i++) {
            loadW(matP1, c0, c1, kk + 8, wt0, wt1);
            fma8(actP1, kk, wp0, wp1, acc);
            loadW(matP1, c0, c1, kk + 16, wp0, wp1);
            fma8(actP1, kk + 8, wt0, wt1, acc);
            kk += 16;
        }
        loadW(matP1, c0, c1, kk + 8, wt0, wt1);
        fma8(actP1, kk, wp0, wp1, acc);
        loadW(Wm, c0, c1, k0m, wp0, wp1);      // prefetch P2 chunk0
        fma8(actP1, kk + 8, wt0, wt1, acc);
    }
    part_store(pD0, pD1, acc);
    __syncthreads();                              // bar1
    {
        // v = slots 0-2 ; g1 pre-act = slots 3-7
        float v0 = pA[p0] + pA[1024 + p0] + pA[2048 + p0];
        float v1 = pA[p1] + pA[1024 + p1] + pA[2048 + p1];
        bufC[p0] = v0 + bv0;
        bufC[p1] = v1 + bv1;
        float x0 = (pA[3072 + p0] + pA[4096 + p0]) + (pA[5120 + p0] + pA[6144 + p0]) + pA[7168 + p0];
        float x1 = (pA[3072 + p1] + pA[4096 + p1]) + (pA[5120 + p1] + pA[6144 + p1]) + pA[7168 + p1];
        x0 += gb10; x1 += gb11;
        g1F[p0] = x0 / (1.0f + __expf(-x0));
        g1F[p1] = x1 / (1.0f + __expf(-x1));
    }
    __syncthreads();                              // bar2

    // ---- P2 merged: slices 0-3 do v@Wo, slices 4-7 do g1@gW2 (32 k each) ----
    {
        const float* actm = (s < 4) ? bufC : g1F;
        GEMM_ZERO();
        loadW(Wm, c0, c1, k0m + 8, wt0, wt1);
        fma8(actm, k0m, wp0, wp1, acc);
        loadW(Wm, c0, c1, k0m + 16, wp0, wp1);
        fma8(actm, k0m + 8, wt0, wt1, acc);
        loadW(Wm, c0, c1, k0m + 24, wt0, wt1);
        fma8(actm, k0m + 16, wp0, wp1, acc);
        loadW(mW1, c0, c1, k0, wp0, wp1);      // prefetch S5 chunk0
        fma8(actm, k0m + 24, wt0, wt1, acc);
        part_store(pD0, pD1, acc);
    }
    __syncthreads();                              // bar3
    {
        float v0 = (pA[p0] + pA[1024 + p0]) + (pA[2048 + p0] + pA[3072 + p0]);
        float v1 = (pA[p1] + pA[1024 + p1]) + (pA[2048 + p1] + pA[3072 + p1]);
        outv0 = (float)NNODES * v0 + bo0;
        outv1 = (float)NNODES * v1 + bo1;
        float x0 = (pA[4096 + p0] + pA[5120 + p0]) + (pA[6144 + p0] + pA[7168 + p0]);
        float x1 = (pA[4096 + p1] + pA[5120 + p1]) + (pA[6144 + p1] + pA[7168 + p1]);
        x0 += gb20; x1 += gb21;
        float g0 = 1.0f / (1.0f + __expf(-x0));
        float g1 = 1.0f / (1.0f + __expf(-x1));
        hcv0 = hvF[p0] + g0 * outv0;
        hcv1 = hvF[p1] + g1 * outv1;
        bufA[p0] = hcv0;                          // h_corr (h_pred dead)
        bufA[p1] = hcv1;
    }
    __syncthreads();                              // bar4

    // ---- S5: m1 = relu(h_corr@mW1_top + h_prev@mW1_bot + mb1) -> bufC ----
    GEMM_ZERO();
    loadW(mW1, c0, c1, k0 + 8, wt0, wt1);
    fma8(bufA, k0, wp0, wp1, acc);
    loadW(mW1 + HID * HID, c0, c1, k0, wp0, wp1);
    fma8(bufA, k0 + 8, wt0, wt1, acc);
    loadW(mW1 + HID * HID, c0, c1, k0 + 8, wt0, wt1);
    fma8(hvF, k0, wp0, wp1, acc);
    loadW(mW2, c0, c1, k0, wp0, wp1);          // prefetch S6 chunk0
    fma8(hvF, k0 + 8, wt0, wt1, acc);
    part_store(pD0, pD1, acc);
    __syncthreads();                              // bar5
    {
        float x0 = ((pA[p0] + pA[1024 + p0]) + (pA[2048 + p0] + pA[3072 + p0]))
                 + ((pA[4096 + p0] + pA[5120 + p0]) + (pA[6144 + p0] + pA[7168 + p0]));
        float x1 = ((pA[p1] + pA[1024 + p1]) + (pA[2048 + p1] + pA[3072 + p1]))
                 + ((pA[4096 + p1] + pA[5120 + p1]) + (pA[6144 + p1] + pA[7168 + p1]));
        bufC[p0] = fmaxf(x0 + mb10, 0.0f);
        bufC[p1] = fmaxf(x1 + mb11, 0.0f);
    }
    __syncthreads();                              // bar6

    // ---- S6: mixed = h_corr + m1 @ mW2 + mb2 -> global ----
    GEMM_ZERO();
    loadW(mW2, c0, c1, k0 + 8, wt0, wt1);
    fma8(bufC, k0, wp0, wp1, acc);
    fma8(bufC, k0 + 8, wt0, wt1, acc);
    part_store(pD0, pD1, acc);
    __syncthreads();                              // bar7
    {
        float v0 = ((pA[p0] + pA[1024 + p0]) + (pA[2048 + p0] + pA[3072 + p0]))
                 + ((pA[4096 + p0] + pA[5120 + p0]) + (pA[6144 + p0] + pA[7168 + p0]));
        float v1 = ((pA[p1] + pA[1024 + p1]) + (pA[2048 + p1] + pA[3072 + p1]))
                 + ((pA[4096 + p1] + pA[5120 + p1]) + (pA[6144 + p1] + pA[7168 + p1]));
        out[(r0 + (p0 & 7)) * HID + q0] = hcv0 + v0 + mb20;
        out[(r0 + (p1 & 7)) * HID + q1] = hcv1 + v1 + mb21;
    }
}

extern "C" void kernel_launch(void* const* d_in, const int* in_sizes, int n_in,
                              void* d_out, int out_size) {
    // metadata order: h_prev, h_pred, adj_rows, adj_cols, Wq, bq, Wk, bk,
    //                 Wv, bv, Wo, bo, gW1, gb1, gW2, gb2, mW1, mb1, mW2, mb2
    const float* h_prev = (const float*)d_in[0];
    const float* h_pred = (const float*)d_in[1];
    // d_in[2..7] (adjacency, Wq/bq/Wk/bk) are algebraically dead.
    const float* Wv  = (const float*)d_in[8];
    const float* bv  = (const float*)d_in[9];
    const float* Wo  = (const float*)d_in[10];
    const float* bo  = (const float*)d_in[11];
    const float* gW1 = (const float*)d_in[12];
    const float* gb1 = (const float*)d_in[13];
    const float* gW2 = (const float*)d_in[14];
    const float* gb2 = (const float*)d_in[15];
    const float* mW1 = (const float*)d_in[16];
    const float* mb1 = (const float*)d_in[17];
    const float* mW2 = (const float*)d_in[18];
    const float* mb2 = (const float*)d_in[19];
    float* out = (float*)d_out;

    temporal_attn_fused<<<NNODES / ROWS, NTHREADS>>>(
        h_prev, h_pred, Wv, bv, Wo, bo,
        gW1, gb1, gW2, gb2, mW1, mb1, mW2, mb2, out);
}

// round 15
// speedup vs baseline: 1.0766x; 1.0766x over previous
#include <cuda_runtime.h>
#include <cuda_bf16.h>
#include <math.h>

// Attention path collapses (softmax rows sum to 1; T,S fully contracted):
//   y = 1024 * (h_pred @ Wv + bv)
// Only Wv/Wo projection + gate MLP + mixer MLP survive. Further:
//   out = hp @ Wcomb + bcomb,  Wcomb = 1024*Wv@Wo (2M FMA, helper kernel),
//   bcomb = 1024*bv@Wo + bo   -> S1/S2 eliminated from the main kernel.
//
// R13: two-kernel plan. Helper computes Wcomb+bcomb into __device__ scratch.
// Main kernel: P1 = {hp@Wcomb, hp@gW1top, hv@gW1bot, hv@mW1bot} balanced
// 8 chunks/slice; then S4 -> S5top -> S6 (2 chunks/slice each). 8 barriers.

#define HID 128
#define ROWS 8
#define SLICES 8
#define NNODES 1024
#define NTHREADS 512

typedef unsigned long long u64;

__device__ float g_Wcomb[(HID + 1) * HID];   // rows 0-127: 1024*Wv@Wo ; row 128: bcomb

// ---------- helper: Wcomb = 1024*Wv@Wo ; bcomb = 1024*bv@Wo + bo ----------
extern "C" __global__ void __launch_bounds__(HID)
wcomb_kernel(const float* __restrict__ Wv, const float* __restrict__ bv,
             const float* __restrict__ Wo, const float* __restrict__ bo) {
    __shared__ float arow[HID];
    const int r = blockIdx.x;        // 0..128 (128 = bias row)
    const int c = threadIdx.x;
    arow[c] = (r < HID) ? Wv[r * HID + c] : bv[c];
    __syncthreads();
    float a0 = 0.f, a1 = 0.f, a2 = 0.f, a3 = 0.f;
#pragma unroll
    for (int k = 0; k < HID; k += 4) {
        a0 += arow[k]     * Wo[(k)     * HID + c];
        a1 += arow[k + 1] * Wo[(k + 1) * HID + c];
        a2 += arow[k + 2] * Wo[(k + 2) * HID + c];
        a3 += arow[k + 3] * Wo[(k + 3) * HID + c];
    }
    float v = (float)NNODES * ((a0 + a1) + (a2 + a3));
    if (r == HID) v += bo[c];
    g_Wcomb[r * HID + c] = v;
}

// ---------- main fused kernel ----------
__device__ __forceinline__ u64 fma2(u64 a, u64 b, u64 c) {
    u64 d;
    asm("fma.rn.f32x2 %0, %1, %2, %3;" : "=l"(d) : "l"(a), "l"(b), "l"(c));
    return d;
}

__device__ __forceinline__ void loadW(const float* __restrict__ W, int c0,
                                      int c1, int k, float w0[8], float w1[8]) {
#pragma unroll
    for (int i = 0; i < 8; i++) {
        w0[i] = W[(k + i) * HID + c0];
        w1[i] = W[(k + i) * HID + c1];
    }
}

// 8 k-steps: two broadcast LDS.128 per k serve 8 FFMA2 (8 rows x 2 cols).
__device__ __forceinline__ void fma8(const float* __restrict__ act, int k,
                                     const float w0[8], const float w1[8],
                                     u64 acc[8]) {
#pragma unroll
    for (int i = 0; i < 8; i++) {
        u64 ww0, ww1;
        asm("mov.b64 %0, {%1, %1};" : "=l"(ww0) : "f"(w0[i]));
        asm("mov.b64 %0, {%1, %1};" : "=l"(ww1) : "f"(w1[i]));
        const ulonglong2* a = (const ulonglong2*)(act + (k + i) * ROWS);
        ulonglong2 a01 = a[0];
        ulonglong2 a23 = a[1];
        acc[0] = fma2(a01.x, ww0, acc[0]);
        acc[1] = fma2(a01.y, ww0, acc[1]);
        acc[2] = fma2(a23.x, ww0, acc[2]);
        acc[3] = fma2(a23.y, ww0, acc[3]);
        acc[4] = fma2(a01.x, ww1, acc[4]);
        acc[5] = fma2(a01.y, ww1, acc[5]);
        acc[6] = fma2(a23.x, ww1, acc[6]);
        acc[7] = fma2(a23.y, ww1, acc[7]);
    }
}

__device__ __forceinline__ void part_store(float* d0, float* d1,
                                           const u64 acc[8]) {
    ((ulonglong2*)d0)[0] = make_ulonglong2(acc[0], acc[1]);
    ((ulonglong2*)d0)[1] = make_ulonglong2(acc[2], acc[3]);
    ((ulonglong2*)d1)[0] = make_ulonglong2(acc[4], acc[5]);
    ((ulonglong2*)d1)[1] = make_ulonglong2(acc[6], acc[7]);
}

extern "C" __global__ void __launch_bounds__(NTHREADS, 1)
temporal_attn_fused(const float* __restrict__ h_prev,
                    const float* __restrict__ h_pred,
                    const float* __restrict__ gW1, const float* __restrict__ gb1,
                    const float* __restrict__ gW2, const float* __restrict__ gb2,
                    const float* __restrict__ mW1, const float* __restrict__ mb1,
                    const float* __restrict__ mW2, const float* __restrict__ mb2,
                    float* __restrict__ out) {
    __shared__ float bufA[HID * ROWS];          // 4KB  h_pred, later h_corr
    __shared__ float hvF[HID * ROWS];           // 4KB  h_prev
    __shared__ float bufC[HID * ROWS];          // 4KB  m1
    __shared__ float g1F[HID * ROWS];           // 4KB  gate hidden
    __shared__ float pA[SLICES * HID * ROWS];   // 32KB partials

    const int tid = threadIdx.x;
    const int lane = tid & 31;
    const int wid = tid >> 5;
    const int s = wid >> 1;                 // k-slice 0..7 (warp-uniform)
    const int c0 = (wid & 1) * 32 + lane;   // first owned column
    const int c1 = c0 + 64;                 // second owned column
    const int k0 = s * 16;                  // P2/P3/P4 k-offset
    const int r0 = blockIdx.x * ROWS;
    const int p0 = tid, p1 = tid + NTHREADS;
    const int q0 = p0 >> 3, q1 = p1 >> 3;

    // Hoisted per-element constants.
    const float bc0 = g_Wcomb[HID * HID + q0], bc1 = g_Wcomb[HID * HID + q1];
    const float gb10 = gb1[q0], gb11 = gb1[q1];
    const float gb20 = gb2[q0], gb21 = gb2[q1];
    const float mb10 = mb1[q0], mb11 = mb1[q1];
    const float mb20 = mb2[q0], mb21 = mb2[q1];

    // P1 schedule (warp-uniform): slices {0,1}=hp@Wcomb, {2,3}=hp@gW1top,
    // {4,5}=hv@gW1bot, {6,7}=hv@mW1bot; each slice 64 k-steps at kb.
    const float* matP1 = (s < 2) ? g_Wcomb
                       : (s < 4) ? gW1
                       : (s < 6) ? (gW1 + HID * HID)
                                 : (mW1 + HID * HID);
    const int kb = (s & 1) * 64;

    float wp0[8], wp1[8], wt0[8], wt1[8];
    loadW(matP1, c0, c1, kb, wp0, wp1);     // P1 chunk0 in flight

    // Stage input tiles transposed: [k][r], coalesced global reads.
#pragma unroll
    for (int j = 0; j < 2; j++) {
        int g = tid + j * NTHREADS;
        int r = g >> 7, cc = g & (HID - 1);
        bufA[cc * ROWS + r] = h_pred[(r0 + r) * HID + cc];
        hvF[cc * ROWS + r]  = h_prev[(r0 + r) * HID + cc];
    }
    __syncthreads();                              // bar0

    u64 acc[8];
    float* pD0 = pA + s * 1024 + c0 * ROWS;
    float* pD1 = pA + s * 1024 + c1 * ROWS;
    const float* actP1 = (s < 4) ? bufA : hvF;

#define GEMM_ZERO() { acc[0]=acc[1]=acc[2]=acc[3]=acc[4]=acc[5]=acc[6]=acc[7]=0ULL; }
#define RED8(x, p)  float x = ((pA[p] + pA[1024 + (p)]) + (pA[2048 + (p)] + pA[3072 + (p)])) \
                            + ((pA[4096 + (p)] + pA[5120 + (p)]) + (pA[6144 + (p)] + pA[7168 + (p)]))

    float outv0, outv1, hcv0, hcv1, m5b0, m5b1;

    // ======== P1: out-GEMM + gate-hidden + mixer-bottom (8 chunks) ========
    GEMM_ZERO();
    loadW(matP1, c0, c1, kb + 8, wt0, wt1);   fma8(actP1, kb,      wp0, wp1, acc);
    loadW(matP1, c0, c1, kb + 16, wp0, wp1);  fma8(actP1, kb + 8,  wt0, wt1, acc);
    loadW(matP1, c0, c1, kb + 24, wt0, wt1);  fma8(actP1, kb + 16, wp0, wp1, acc);
    loadW(matP1, c0, c1, kb + 32, wp0, wp1);  fma8(actP1, kb + 24, wt0, wt1, acc);
    loadW(matP1, c0, c1, kb + 40, wt0, wt1);  fma8(actP1, kb + 32, wp0, wp1, acc);
    loadW(matP1, c0, c1, kb + 48, wp0, wp1);  fma8(actP1, kb + 40, wt0, wt1, acc);
    loadW(matP1, c0, c1, kb + 56, wt0, wt1);  fma8(actP1, kb + 48, wp0, wp1, acc);
    loadW(gW2, c0, c1, k0, wp0, wp1);         fma8(actP1, kb + 56, wt0, wt1, acc);
    part_store(pD0, pD1, acc);
    __syncthreads();                              // bar1
    {
        // out = slots 0-1 + bcomb (register-carried)
        outv0 = (pA[p0] + pA[1024 + p0]) + bc0;
        outv1 = (pA[p1] + pA[1024 + p1]) + bc1;
        // g1 = slots 2-5 + gb1, silu
        float x0 = (pA[2048 + p0] + pA[3072 + p0]) + (pA[4096 + p0] + pA[5120 + p0]) + gb10;
        float x1 = (pA[2048 + p1] + pA[3072 + p1]) + (pA[4096 + p1] + pA[5120 + p1]) + gb11;
        g1F[p0] = x0 / (1.0f + __expf(-x0));
        g1F[p1] = x1 / (1.0f + __expf(-x1));
        // mixer-bottom partial = slots 6-7 (register-carried to P3)
        m5b0 = pA[6144 + p0] + pA[7168 + p0];
        m5b1 = pA[6144 + p1] + pA[7168 + p1];
    }
    __syncthreads();                              // bar2

    // ======== P2: S4 gate = sigmoid(g1@gW2 + gb2); h_corr ========
    GEMM_ZERO();
    loadW(gW2, c0, c1, k0 + 8, wt0, wt1);  fma8(g1F, k0,     wp0, wp1, acc);
    loadW(mW1, c0, c1, k0, wp0, wp1);      fma8(g1F, k0 + 8, wt0, wt1, acc);
    part_store(pD0, pD1, acc);
    __syncthreads();                              // bar3
    {
        RED8(x0, p0); x0 += gb20;
        RED8(x1, p1); x1 += gb21;
        float g0 = 1.0f / (1.0f + __expf(-x0));
        float g1 = 1.0f / (1.0f + __expf(-x1));
        hcv0 = hvF[p0] + g0 * outv0;
        hcv1 = hvF[p1] + g1 * outv1;
        bufA[p0] = hcv0;                          // h_corr (h_pred dead)
        bufA[p1] = hcv1;
    }
    __syncthreads();                              // bar4

    // ======== P3: S5top m1 = relu(hc@mW1top + m5b + mb1) ========
    GEMM_ZERO();
    loadW(mW1, c0, c1, k0 + 8, wt0, wt1);  fma8(bufA, k0,     wp0, wp1, acc);
    loadW(mW2, c0, c1, k0, wp0, wp1);      fma8(bufA, k0 + 8, wt0, wt1, acc);
    part_store(pD0, pD1, acc);
    __syncthreads();                              // bar5
    {
        RED8(x0, p0); bufC[p0] = fmaxf(x0 + m5b0 + mb10, 0.0f);
        RED8(x1, p1); bufC[p1] = fmaxf(x1 + m5b1 + mb11, 0.0f);
    }
    __syncthreads();                              // bar6

    // ======== P4: S6 mixed = h_corr + m1@mW2 + mb2 -> global ========
    GEMM_ZERO();
    loadW(mW2, c0, c1, k0 + 8, wt0, wt1);  fma8(bufC, k0,     wp0, wp1, acc);
    fma8(bufC, k0 + 8, wt0, wt1, acc);
    part_store(pD0, pD1, acc);
    __syncthreads();                              // bar7
    {
        RED8(v0, p0);
        out[(r0 + (p0 & 7)) * HID + q0] = hcv0 + v0 + mb20;
        RED8(v1, p1);
        out[(r0 + (p1 & 7)) * HID + q1] = hcv1 + v1 + mb21;
    }
}

extern "C" void kernel_launch(void* const* d_in, const int* in_sizes, int n_in,
                              void* d_out, int out_size) {
    // metadata order: h_prev, h_pred, adj_rows, adj_cols, Wq, bq, Wk, bk,
    //                 Wv, bv, Wo, bo, gW1, gb1, gW2, gb2, mW1, mb1, mW2, mb2
    const float* h_prev = (const float*)d_in[0];
    const float* h_pred = (const float*)d_in[1];
    // d_in[2..7] (adjacency, Wq/bq/Wk/bk) are algebraically dead.
    const float* Wv  = (const float*)d_in[8];
    const float* bv  = (const float*)d_in[9];
    const float* Wo  = (const float*)d_in[10];
    const float* bo  = (const float*)d_in[11];
    const float* gW1 = (const float*)d_in[12];
    const float* gb1 = (const float*)d_in[13];
    const float* gW2 = (const float*)d_in[14];
    const float* gb2 = (const float*)d_in[15];
    const float* mW1 = (const float*)d_in[16];
    const float* mb1 = (const float*)d_in[17];
    const float* mW2 = (const float*)d_in[18];
    const float* mb2 = (const float*)d_in[19];
    float* out = (float*)d_out;

    wcomb_kernel<<<HID + 1, HID>>>(Wv, bv, Wo, bo);
    temporal_attn_fused<<<NNODES / ROWS, NTHREADS>>>(
        h_prev, h_pred, gW1, gb1, gW2, gb2, mW1, mb1, mW2, mb2, out);
}

// round 16
// speedup vs baseline: 1.2468x; 1.1580x over previous
#include <cuda_runtime.h>
#include <cuda_bf16.h>
#include <math.h>

// Attention path collapses (softmax rows sum to 1; T,S fully contracted):
//   y = 1024 * (h_pred @ Wv + bv)
// Only Wv/Wo projection + gate MLP + mixer MLP survive.
//
// R14: R13's balanced 4-phase graph WITHOUT the helper kernel.
//   P1 (8 chunks/slice): {hp@Wv, hp@gW1top, hv@gW1bot, hv@mW1bot}
//   P2 (4 chunks):       {v@Wo | g1@gW2} merged across slice halves
//   P3 (2 chunks):       hc@mW1top   (mixer-bottom carried from P1)
//   P4 (2 chunks):       m1@mW2
// 9 barriers, single 32KB partial buffer, 48KB static smem, one launch.

#define HID 128
#define ROWS 8
#define SLICES 8
#define NNODES 1024
#define NTHREADS 512

typedef unsigned long long u64;

__device__ __forceinline__ u64 fma2(u64 a, u64 b, u64 c) {
    u64 d;
    asm("fma.rn.f32x2 %0, %1, %2, %3;" : "=l"(d) : "l"(a), "l"(b), "l"(c));
    return d;
}

__device__ __forceinline__ void loadW(const float* __restrict__ W, int c0,
                                      int c1, int k, float w0[8], float w1[8]) {
#pragma unroll
    for (int i = 0; i < 8; i++) {
        w0[i] = W[(k + i) * HID + c0];
        w1[i] = W[(k + i) * HID + c1];
    }
}

// 8 k-steps: two broadcast LDS.128 per k serve 8 FFMA2 (8 rows x 2 cols).
__device__ __forceinline__ void fma8(const float* __restrict__ act, int k,
                                     const float w0[8], const float w1[8],
                                     u64 acc[8]) {
#pragma unroll
    for (int i = 0; i < 8; i++) {
        u64 ww0, ww1;
        asm("mov.b64 %0, {%1, %1};" : "=l"(ww0) : "f"(w0[i]));
        asm("mov.b64 %0, {%1, %1};" : "=l"(ww1) : "f"(w1[i]));
        const ulonglong2* a = (const ulonglong2*)(act + (k + i) * ROWS);
        ulonglong2 a01 = a[0];
        ulonglong2 a23 = a[1];
        acc[0] = fma2(a01.x, ww0, acc[0]);
        acc[1] = fma2(a01.y, ww0, acc[1]);
        acc[2] = fma2(a23.x, ww0, acc[2]);
        acc[3] = fma2(a23.y, ww0, acc[3]);
        acc[4] = fma2(a01.x, ww1, acc[4]);
        acc[5] = fma2(a01.y, ww1, acc[5]);
        acc[6] = fma2(a23.x, ww1, acc[6]);
        acc[7] = fma2(a23.y, ww1, acc[7]);
    }
}

__device__ __forceinline__ void part_store(float* d0, float* d1,
                                           const u64 acc[8]) {
    ((ulonglong2*)d0)[0] = make_ulonglong2(acc[0], acc[1]);
    ((ulonglong2*)d0)[1] = make_ulonglong2(acc[2], acc[3]);
    ((ulonglong2*)d1)[0] = make_ulonglong2(acc[4], acc[5]);
    ((ulonglong2*)d1)[1] = make_ulonglong2(acc[6], acc[7]);
}

extern "C" __global__ void __launch_bounds__(NTHREADS, 1)
temporal_attn_fused(const float* __restrict__ h_prev,
                    const float* __restrict__ h_pred,
                    const float* __restrict__ Wv, const float* __restrict__ bv,
                    const float* __restrict__ Wo, const float* __restrict__ bo,
                    const float* __restrict__ gW1, const float* __restrict__ gb1,
                    const float* __restrict__ gW2, const float* __restrict__ gb2,
                    const float* __restrict__ mW1, const float* __restrict__ mb1,
                    const float* __restrict__ mW2, const float* __restrict__ mb2,
                    float* __restrict__ out) {
    __shared__ float bufA[HID * ROWS];          // 4KB  h_pred, later h_corr
    __shared__ float hvF[HID * ROWS];           // 4KB  h_prev
    __shared__ float bufC[HID * ROWS];          // 4KB  v, later m1
    __shared__ float g1F[HID * ROWS];           // 4KB  gate hidden
    __shared__ float pA[SLICES * HID * ROWS];   // 32KB partials

    const int tid = threadIdx.x;
    const int lane = tid & 31;
    const int wid = tid >> 5;
    const int s = wid >> 1;                 // k-slice 0..7 (warp-uniform)
    const int c0 = (wid & 1) * 32 + lane;   // first owned column
    const int c1 = c0 + 64;                 // second owned column
    const int k0 = s * 16;                  // P3/P4 k-offset
    const int r0 = blockIdx.x * ROWS;
    const int p0 = tid, p1 = tid + NTHREADS;
    const int q0 = p0 >> 3, q1 = p1 >> 3;

    // Hoisted per-element constants.
    const float bv0 = bv[q0], bv1 = bv[q1];
    const float bo0 = bo[q0], bo1 = bo[q1];
    const float gb10 = gb1[q0], gb11 = gb1[q1];
    const float gb20 = gb2[q0], gb21 = gb2[q1];
    const float mb10 = mb1[q0], mb11 = mb1[q1];
    const float mb20 = mb2[q0], mb21 = mb2[q1];

    // P1 schedule (warp-uniform): slices {0,1}=hp@Wv, {2,3}=hp@gW1top,
    // {4,5}=hv@gW1bot, {6,7}=hv@mW1bot; each slice 64 k-steps at kb.
    const float* matP1 = (s < 2) ? Wv
                       : (s < 4) ? gW1
                       : (s < 6) ? (gW1 + HID * HID)
                                 : (mW1 + HID * HID);
    const int kb = (s & 1) * 64;

    // P2 schedule: slices 0-3 do v@Wo, slices 4-7 do g1@gW2; 32 k each.
    const float* Wm = (s < 4) ? Wo : gW2;
    const int k0m = (s & 3) * 32;

    float wp0[8], wp1[8], wt0[8], wt1[8];
    loadW(matP1, c0, c1, kb, wp0, wp1);     // P1 chunk0 in flight

    // Stage input tiles transposed: [k][r], coalesced global reads.
#pragma unroll
    for (int j = 0; j < 2; j++) {
        int g = tid + j * NTHREADS;
        int r = g >> 7, cc = g & (HID - 1);
        bufA[cc * ROWS + r] = h_pred[(r0 + r) * HID + cc];
        hvF[cc * ROWS + r]  = h_prev[(r0 + r) * HID + cc];
    }
    __syncthreads();                              // bar0

    u64 acc[8];
    float* pD0 = pA + s * 1024 + c0 * ROWS;
    float* pD1 = pA + s * 1024 + c1 * ROWS;
    const float* actP1 = (s < 4) ? bufA : hvF;

#define GEMM_ZERO() { acc[0]=acc[1]=acc[2]=acc[3]=acc[4]=acc[5]=acc[6]=acc[7]=0ULL; }
#define RED8(x, p)  float x = ((pA[p] + pA[1024 + (p)]) + (pA[2048 + (p)] + pA[3072 + (p)])) \
                            + ((pA[4096 + (p)] + pA[5120 + (p)]) + (pA[6144 + (p)] + pA[7168 + (p)]))

    float outv0, outv1, hcv0, hcv1, m5b0, m5b1;

    // ======== P1: v-GEMM + gate-hidden + mixer-bottom (8 chunks) ========
    GEMM_ZERO();
    loadW(matP1, c0, c1, kb + 8, wt0, wt1);   fma8(actP1, kb,      wp0, wp1, acc);
    loadW(matP1, c0, c1, kb + 16, wp0, wp1);  fma8(actP1, kb + 8,  wt0, wt1, acc);
    loadW(matP1, c0, c1, kb + 24, wt0, wt1);  fma8(actP1, kb + 16, wp0, wp1, acc);
    loadW(matP1, c0, c1, kb + 32, wp0, wp1);  fma8(actP1, kb + 24, wt0, wt1, acc);
    loadW(matP1, c0, c1, kb + 40, wt0, wt1);  fma8(actP1, kb + 32, wp0, wp1, acc);
    loadW(matP1, c0, c1, kb + 48, wp0, wp1);  fma8(actP1, kb + 40, wt0, wt1, acc);
    loadW(matP1, c0, c1, kb + 56, wt0, wt1);  fma8(actP1, kb + 48, wp0, wp1, acc);
    loadW(Wm, c0, c1, k0m, wp0, wp1);         fma8(actP1, kb + 56, wt0, wt1, acc);
    part_store(pD0, pD1, acc);
    __syncthreads();                              // bar1
    {
        // v = slots 0-1 + bv -> bufC
        bufC[p0] = (pA[p0] + pA[1024 + p0]) + bv0;
        bufC[p1] = (pA[p1] + pA[1024 + p1]) + bv1;
        // g1 = slots 2-5 + gb1, silu -> g1F
        float x0 = (pA[2048 + p0] + pA[3072 + p0]) + (pA[4096 + p0] + pA[5120 + p0]) + gb10;
        float x1 = (pA[2048 + p1] + pA[3072 + p1]) + (pA[4096 + p1] + pA[5120 + p1]) + gb11;
        g1F[p0] = x0 / (1.0f + __expf(-x0));
        g1F[p1] = x1 / (1.0f + __expf(-x1));
        // mixer-bottom partial = slots 6-7 (register-carried to P3)
        m5b0 = pA[6144 + p0] + pA[7168 + p0];
        m5b1 = pA[6144 + p1] + pA[7168 + p1];
    }
    __syncthreads();                              // bar2

    // ======== P2 merged: S2 (v@Wo, slices 0-3) | S4 (g1@gW2, slices 4-7) ====
    {
        const float* actm = (s < 4) ? bufC : g1F;
        GEMM_ZERO();
        loadW(Wm, c0, c1, k0m + 8, wt0, wt1);   fma8(actm, k0m,      wp0, wp1, acc);
        loadW(Wm, c0, c1, k0m + 16, wp0, wp1);  fma8(actm, k0m + 8,  wt0, wt1, acc);
        loadW(Wm, c0, c1, k0m + 24, wt0, wt1);  fma8(actm, k0m + 16, wp0, wp1, acc);
        loadW(mW1, c0, c1, k0, wp0, wp1);       fma8(actm, k0m + 24, wt0, wt1, acc);
        part_store(pD0, pD1, acc);
    }
    __syncthreads();                              // bar3
    {
        // out = 1024*(slots 0-3) + bo (register-carried)
        float v0 = (pA[p0] + pA[1024 + p0]) + (pA[2048 + p0] + pA[3072 + p0]);
        float v1 = (pA[p1] + pA[1024 + p1]) + (pA[2048 + p1] + pA[3072 + p1]);
        outv0 = (float)NNODES * v0 + bo0;
        outv1 = (float)NNODES * v1 + bo1;
        // gate = sigmoid(slots 4-7 + gb2); h_corr = hv + gate*out
        float x0 = (pA[4096 + p0] + pA[5120 + p0]) + (pA[6144 + p0] + pA[7168 + p0]) + gb20;
        float x1 = (pA[4096 + p1] + pA[5120 + p1]) + (pA[6144 + p1] + pA[7168 + p1]) + gb21;
        float g0 = 1.0f / (1.0f + __expf(-x0));
        float g1 = 1.0f / (1.0f + __expf(-x1));
        hcv0 = hvF[p0] + g0 * outv0;
        hcv1 = hvF[p1] + g1 * outv1;
        bufA[p0] = hcv0;                          // h_corr (h_pred dead)
        bufA[p1] = hcv1;
    }
    __syncthreads();                              // bar4

    // ======== P3: S5top m1 = relu(hc@mW1top + m5b + mb1) -> bufC ========
    GEMM_ZERO();
    loadW(mW1, c0, c1, k0 + 8, wt0, wt1);  fma8(bufA, k0,     wp0, wp1, acc);
    loadW(mW2, c0, c1, k0, wp0, wp1);      fma8(bufA, k0 + 8, wt0, wt1, acc);
    part_store(pD0, pD1, acc);
    __syncthreads();                              // bar5
    {
        RED8(x0, p0); bufC[p0] = fmaxf(x0 + m5b0 + mb10, 0.0f);
        RED8(x1, p1); bufC[p1] = fmaxf(x1 + m5b1 + mb11, 0.0f);
    }
    __syncthreads();                              // bar6

    // ======== P4: S6 mixed = h_corr + m1@mW2 + mb2 -> global ========
    GEMM_ZERO();
    loadW(mW2, c0, c1, k0 + 8, wt0, wt1);  fma8(bufC, k0,     wp0, wp1, acc);
    fma8(bufC, k0 + 8, wt0, wt1, acc);
    part_store(pD0, pD1, acc);
    __syncthreads();                              // bar7
    {
        RED8(v0, p0);
        out[(r0 + (p0 & 7)) * HID + q0] = hcv0 + v0 + mb20;
        RED8(v1, p1);
        out[(r0 + (p1 & 7)) * HID + q1] = hcv1 + v1 + mb21;
    }
}

extern "C" void kernel_launch(void* const* d_in, const int* in_sizes, int n_in,
                              void* d_out, int out_size) {
    // metadata order: h_prev, h_pred, adj_rows, adj_cols, Wq, bq, Wk, bk,
    //                 Wv, bv, Wo, bo, gW1, gb1, gW2, gb2, mW1, mb1, mW2, mb2
    const float* h_prev = (const float*)d_in[0];
    const float* h_pred = (const float*)d_in[1];
    // d_in[2..7] (adjacency, Wq/bq/Wk/bk) are algebraically dead.
    const float* Wv  = (const float*)d_in[8];
    const float* bv  = (const float*)d_in[9];
    const float* Wo  = (const float*)d_in[10];
    const float* bo  = (const float*)d_in[11];
    const float* gW1 = (const float*)d_in[12];
    const float* gb1 = (const float*)d_in[13];
    const float* gW2 = (const float*)d_in[14];
    const float* gb2 = (const float*)d_in[15];
    const float* mW1 = (const float*)d_in[16];
    const float* mb1 = (const float*)d_in[17];
    const float* mW2 = (const float*)d_in[18];
    const float* mb2 = (const float*)d_in[19];
    float* out = (float*)d_out;

    temporal_attn_fused<<<NNODES / ROWS, NTHREADS>>>(
        h_prev, h_pred, Wv, bv, Wo, bo,
        gW1, gb1, gW2, gb2, mW1, mb1, mW2, mb2, out);
}